// round 8
// baseline (speedup 1.0000x reference)
#include <cuda_runtime.h>
#include <cuda_fp16.h>
#include <cstdint>

// ---------------- problem constants ----------------
#define B_    16
#define CIN   32
#define COUT  64
#define HO    62
#define WO    62
#define HW    4096
#define KDIM  288          // (c,g) = 32*9
#define MTOT  65536        // b*h*w pixels
#define MPAD  65800
#define MOUT  62           // output rows per CTA (M-tile 64, minus halo 2)
#define NCTA  1058         // ceil(65536/62)

// ---------------- device scratch ----------------
__device__ __align__(16) __half g_A[(size_t)MPAD * KDIM];   // fp16 features
__device__ __align__(16) __half g_B[9 * 64 * KDIM];         // [tap][n][k] fp16

// ---------------- helpers ----------------
__device__ __forceinline__ uint32_t smem_u32(const void* p) {
    uint32_t a;
    asm("{ .reg .u64 t; cvta.to.shared.u64 t, %1; cvt.u32.u64 %0, t; }" : "=r"(a) : "l"(p));
    return a;
}
__device__ __forceinline__ void cp16(uint32_t dst, const void* src) {
    asm volatile("cp.async.cg.shared.global [%0], [%1], 16;" :: "r"(dst), "l"(src));
}
#define CP_COMMIT() asm volatile("cp.async.commit_group;" ::: "memory")
#define CP_WAIT1()  asm volatile("cp.async.wait_group 1;" ::: "memory")
#define CP_WAITALL() asm volatile("cp.async.wait_all;" ::: "memory")

#define LDSM4(r, a)                                                          \
    asm volatile("ldmatrix.sync.aligned.m8n8.x4.shared.b16 {%0,%1,%2,%3}, [%4];" \
        : "=r"((r)[0]), "=r"((r)[1]), "=r"((r)[2]), "=r"((r)[3]) : "r"(a))
#define LDSM2(r, a)                                                          \
    asm volatile("ldmatrix.sync.aligned.m8n8.x2.shared.b16 {%0,%1}, [%2];"   \
        : "=r"((r)[0]), "=r"((r)[1]) : "r"(a))
#define MMA(d, a, b)                                                         \
    asm volatile("mma.sync.aligned.m16n8k16.row.col.f32.f16.f16.f32 "        \
        "{%0,%1,%2,%3}, {%4,%5,%6,%7}, {%8,%9}, {%0,%1,%2,%3};"              \
        : "+f"((d)[0]), "+f"((d)[1]), "+f"((d)[2]), "+f"((d)[3])             \
        : "r"((a)[0]), "r"((a)[1]), "r"((a)[2]), "r"((a)[3]),                \
          "r"((b)[0]), "r"((b)[1]))

// ---------------- feature math (constant-reciprocal Cox-de Boor) ----------
__device__ __forceinline__ void features9(float v, float f[9]) {
    f[0] = __fdividef(v, 1.0f + __expf(-v));   // SiLU
    float t[12];
#pragma unroll
    for (int j = 0; j < 12; ++j) t[j] = (float)(j - 3) * 0.4f + (-1.0f);
    float b0[11];
#pragma unroll
    for (int i = 0; i < 11; ++i) b0[i] = (v >= t[i] && v < t[i + 1]) ? 1.0f : 0.0f;
    const float r1 = 2.5f;
    const float r2 = 1.25f;
    const float r3 = 1.0f / 1.2f;
    float b1[10];
#pragma unroll
    for (int i = 0; i < 10; ++i)
        b1[i] = (v - t[i]) * r1 * b0[i] + (t[i + 2] - v) * r1 * b0[i + 1];
    float b2[9];
#pragma unroll
    for (int i = 0; i < 9; ++i)
        b2[i] = (v - t[i]) * r2 * b1[i] + (t[i + 3] - v) * r2 * b1[i + 1];
#pragma unroll
    for (int i = 0; i < 8; ++i)
        f[i + 1] = (v - t[i]) * r3 * b2[i] + (t[i + 4] - v) * r3 * b2[i + 1];
}

// ---------------- kernel 1: features -> fp16 A (coalesced) ----------------
#define SROW 290
__global__ void __launch_bounds__(256) feat_kernel(const float* __restrict__ x) {
    __shared__ __half SA[32][SROW];
    const int m0  = blockIdx.x * 32;
    const int b   = m0 >> 12;
    const int hw0 = m0 & 4095;
    const int t   = threadIdx.x;
    const int i   = t & 31;
    const int c0  = t >> 5;

#pragma unroll
    for (int cc = 0; cc < 4; ++cc) {
        int c = c0 + cc * 8;
        float v = x[((size_t)(b * CIN + c) << 12) + hw0 + i];
        float f[9];
        features9(v, f);
#pragma unroll
        for (int g = 0; g < 9; ++g) SA[i][c * 9 + g] = __float2half(f[g]);
    }
    __syncthreads();

#pragma unroll
    for (int u = t; u < 1152; u += 256) {
        int row = u / 36;
        int col = (u - row * 36) * 8;
        const uint32_t* pa = (const uint32_t*)&SA[row][col];
        uint4 va; va.x = pa[0]; va.y = pa[1]; va.z = pa[2]; va.w = pa[3];
        *(uint4*)&g_A[(size_t)(m0 + row) * KDIM + col] = va;
    }
}

// ---------------- kernel 2: fold weights -> fp16 ----------------
__global__ void fold_kernel(const float* __restrict__ bw,
                            const float* __restrict__ sw,
                            const float* __restrict__ ss) {
    int i = blockIdx.x * blockDim.x + threadIdx.x;    // [tap][n][k]
    if (i >= 9 * 64 * KDIM) return;
    int k = i % KDIM;
    int n = (i / KDIM) & 63;
    int p = i / (KDIM * 64);
    int c = k / 9, g = k % 9;
    int ocp = (n * CIN + c) * 9 + p;
    float val = (g == 0) ? bw[ocp] : sw[ocp * 8 + (g - 1)] * ss[ocp];
    g_B[i] = __float2half(val);
}

// ---------------- kernel 3: mma.sync fp16 GEMM, M-tile 64, occ 2 ----------
// smem per buffer: A[192 rows][48B pitch]  = 9216
//                  B[9 tiles][64 rows][48] = 27648
// double buffered: 2 * 36864 = 73728; epilogue needs 3*64*65*4 = 49920.
#define APITCH 48
#define BOFF   (192 * APITCH)            // 9216
#define BTILE  (64 * APITCH)             // 3072
#define BUFSZ  (BOFF + 9 * BTILE)        // 36864
#define SMEM_TOT (2 * BUFSZ)             // 73728

__global__ void __launch_bounds__(256, 2) gemm_kernel(float* __restrict__ out) {
    extern __shared__ __align__(16) char smem[];
    uint32_t sb = smem_u32(smem);
    const int tid  = threadIdx.x;
    const int lane = tid & 31;
    const int wid  = tid >> 5;
    const int mw = wid & 1;              // m-warp: rows mw*32..+32
    const int nw = wid >> 1;             // n-warp: cols nw*16..+16
    const int m0 = blockIdx.x * MOUT;

    const char* Ap = (const char*)g_A;
    const char* Bp = (const char*)g_B;

    // per-kc: A 192 rows x 2 halves = 384, B 9*64*2 = 1152 -> 1536 = 6*256
    auto prefetch = [&](int kc, uint32_t bb) {
#pragma unroll
        for (int i = 0; i < 6; ++i) {
            int u = tid + i * 256;
            const char* src;
            uint32_t dst;
            if (u < 384) {
                int row = u >> 1, half = u & 1;
                src = Ap + (size_t)(m0 + row) * (KDIM * 2) + kc * 32 + half * 16;
                dst = bb + row * APITCH + half * 16;
            } else {
                int v = u - 384;
                int tile = v >> 7, row = (v >> 1) & 63, half = v & 1;
                src = Bp + (size_t)(tile * 64 + row) * (KDIM * 2) + kc * 32 + half * 16;
                dst = bb + BOFF + tile * BTILE + row * APITCH + half * 16;
            }
            cp16(dst, src);
        }
    };

    float acc[3][2][2][4];               // [kw][t2][nf][4]
#pragma unroll
    for (int a = 0; a < 3; ++a)
#pragma unroll
        for (int b = 0; b < 2; ++b)
#pragma unroll
            for (int c = 0; c < 2; ++c)
#pragma unroll
                for (int d = 0; d < 4; ++d) acc[a][b][c][d] = 0.0f;

    const uint32_t a_lane = (uint32_t)((lane & 15) * APITCH + (lane >> 4) * 16);
    const uint32_t b_lane = (uint32_t)((lane & 7) * APITCH + ((lane >> 3) & 1) * 16);

    prefetch(0, sb);
    CP_COMMIT();

    for (int kc = 0; kc < 18; ++kc) {
        if (kc < 17) prefetch(kc + 1, sb + ((kc + 1) & 1) * BUFSZ);
        CP_COMMIT();
        CP_WAIT1();
        __syncthreads();

        const uint32_t bb = sb + (kc & 1) * BUFSZ;
#pragma unroll
        for (int kh = 0; kh < 3; ++kh) {
            uint32_t ah[2][4];
#pragma unroll
            for (int t2 = 0; t2 < 2; ++t2) {
                uint32_t ra = bb + (kh * 64 + mw * 32 + t2 * 16) * APITCH + a_lane;
                LDSM4(ah[t2], ra);
            }
#pragma unroll
            for (int kw = 0; kw < 3; ++kw) {
                const int tile = kh * 3 + kw;
#pragma unroll
                for (int nf = 0; nf < 2; ++nf) {
                    uint32_t rb = bb + BOFF + tile * BTILE
                                + (nw * 16 + nf * 8) * APITCH + b_lane;
                    uint32_t bfr[2];
                    LDSM2(bfr, rb);
#pragma unroll
                    for (int t2 = 0; t2 < 2; ++t2)
                        MMA(acc[kw][t2][nf], ah[t2], bfr);
                }
            }
        }
        __syncthreads();
    }

    CP_WAITALL();
    __syncthreads();

    // ---- epilogue: planes D0/D1/D2 [64][65] f32, then shifted sum ----
    float* S = (float*)smem;
    const int grp = lane >> 2;
    const int cq  = (lane & 3) * 2;
#pragma unroll
    for (int kw = 0; kw < 3; ++kw) {
        float* P = S + kw * (64 * 65);
#pragma unroll
        for (int t2 = 0; t2 < 2; ++t2)
#pragma unroll
            for (int nf = 0; nf < 2; ++nf) {
                int row = mw * 32 + t2 * 16 + grp;
                int col = nw * 16 + nf * 8 + cq;
                P[row * 65 + col]           = acc[kw][t2][nf][0];
                P[row * 65 + col + 1]       = acc[kw][t2][nf][1];
                P[(row + 8) * 65 + col]     = acc[kw][t2][nf][2];
                P[(row + 8) * 65 + col + 1] = acc[kw][t2][nf][3];
            }
    }
    __syncthreads();

#pragma unroll
    for (int i = 0; i < 16; ++i) {
        int e = tid + i * 256;               // e < 4096
        int o = e >> 6, r = e & 63;
        if (r < MOUT) {
            int m = m0 + r;
            if (m < MTOT) {
                int h = (m >> 6) & 63, w = m & 63, b = m >> 12;
                if (h < HO && w < WO) {
                    float val = S[r * 65 + o]
                              + S[64 * 65 + (r + 1) * 65 + o]
                              + S[2 * 64 * 65 + (r + 2) * 65 + o];
                    out[(((size_t)(b * COUT + o)) * HO + h) * WO + w] = val;
                }
            }
        }
    }
}

// ---------------- launch ----------------
extern "C" void kernel_launch(void* const* d_in, const int* in_sizes, int n_in,
                              void* d_out, int out_size) {
    const float* x  = (const float*)d_in[0];
    const float* bw = (const float*)d_in[1];
    const float* sw = (const float*)d_in[2];
    const float* ss = (const float*)d_in[3];
    float* out = (float*)d_out;

    static int smem_set = 0;
    if (!smem_set) {
        cudaFuncSetAttribute(gemm_kernel, cudaFuncAttributeMaxDynamicSharedMemorySize, SMEM_TOT);
        smem_set = 1;
    }

    feat_kernel<<<MTOT / 32, 256>>>(x);
    fold_kernel<<<(9 * 64 * KDIM + 255) / 256, 256>>>(bw, sw, ss);
    gemm_kernel<<<NCTA, 256, SMEM_TOT>>>(out);
}

// round 9
// speedup vs baseline: 1.2142x; 1.2142x over previous
#include <cuda_runtime.h>
#include <cuda_fp16.h>
#include <cstdint>

// ---------------- problem constants ----------------
#define B_    16
#define CIN   32
#define COUT  64
#define HO    62
#define WO    62
#define HW    4096
#define KDIM  288          // (c,g) = 32*9
#define MTOT  65536        // b*h*w pixels
#define MPAD  65800
#define MOUT  126          // output rows per CTA
#define NCTA  521

// ---------------- device scratch ----------------
__device__ __align__(16) __half g_A[(size_t)MPAD * KDIM];   // fp16 features
__device__ __align__(16) __half g_B[9 * 64 * KDIM];         // [tap][n][k] fp16

// ---------------- helpers ----------------
__device__ __forceinline__ uint32_t smem_u32(const void* p) {
    uint32_t a;
    asm("{ .reg .u64 t; cvta.to.shared.u64 t, %1; cvt.u32.u64 %0, t; }" : "=r"(a) : "l"(p));
    return a;
}
__device__ __forceinline__ void cp16(uint32_t dst, const void* src) {
    asm volatile("cp.async.cg.shared.global [%0], [%1], 16;" :: "r"(dst), "l"(src));
}
#define CP_COMMIT() asm volatile("cp.async.commit_group;" ::: "memory")
#define CP_WAIT1()  asm volatile("cp.async.wait_group 1;" ::: "memory")
#define CP_WAITALL() asm volatile("cp.async.wait_all;" ::: "memory")

#define LDSM4(r, a)                                                          \
    asm volatile("ldmatrix.sync.aligned.m8n8.x4.shared.b16 {%0,%1,%2,%3}, [%4];" \
        : "=r"((r)[0]), "=r"((r)[1]), "=r"((r)[2]), "=r"((r)[3]) : "r"(a))
#define LDSM2(r, a)                                                          \
    asm volatile("ldmatrix.sync.aligned.m8n8.x2.shared.b16 {%0,%1}, [%2];"   \
        : "=r"((r)[0]), "=r"((r)[1]) : "r"(a))
#define MMA(d, a, b)                                                         \
    asm volatile("mma.sync.aligned.m16n8k16.row.col.f32.f16.f16.f32 "        \
        "{%0,%1,%2,%3}, {%4,%5,%6,%7}, {%8,%9}, {%0,%1,%2,%3};"              \
        : "+f"((d)[0]), "+f"((d)[1]), "+f"((d)[2]), "+f"((d)[3])             \
        : "r"((a)[0]), "r"((a)[1]), "r"((a)[2]), "r"((a)[3]),                \
          "r"((b)[0]), "r"((b)[1]))

// ---------------- feature math (constant-reciprocal Cox-de Boor) ----------
__device__ __forceinline__ void features9(float v, float f[9]) {
    f[0] = __fdividef(v, 1.0f + __expf(-v));   // SiLU
    float t[12];
#pragma unroll
    for (int j = 0; j < 12; ++j) t[j] = (float)(j - 3) * 0.4f + (-1.0f);
    float b0[11];
#pragma unroll
    for (int i = 0; i < 11; ++i) b0[i] = (v >= t[i] && v < t[i + 1]) ? 1.0f : 0.0f;
    const float r1 = 2.5f;
    const float r2 = 1.25f;
    const float r3 = 1.0f / 1.2f;
    float b1[10];
#pragma unroll
    for (int i = 0; i < 10; ++i)
        b1[i] = (v - t[i]) * r1 * b0[i] + (t[i + 2] - v) * r1 * b0[i + 1];
    float b2[9];
#pragma unroll
    for (int i = 0; i < 9; ++i)
        b2[i] = (v - t[i]) * r2 * b1[i] + (t[i + 3] - v) * r2 * b1[i + 1];
#pragma unroll
    for (int i = 0; i < 8; ++i)
        f[i + 1] = (v - t[i]) * r3 * b2[i] + (t[i + 4] - v) * r3 * b2[i + 1];
}

// ---------------- kernel 1: features -> fp16 A (coalesced) ----------------
#define SROW 290
__global__ void __launch_bounds__(256) feat_kernel(const float* __restrict__ x) {
    __shared__ __half SA[32][SROW];
    const int m0  = blockIdx.x * 32;
    const int b   = m0 >> 12;
    const int hw0 = m0 & 4095;
    const int t   = threadIdx.x;
    const int i   = t & 31;
    const int c0  = t >> 5;

#pragma unroll
    for (int cc = 0; cc < 4; ++cc) {
        int c = c0 + cc * 8;
        float v = x[((size_t)(b * CIN + c) << 12) + hw0 + i];
        float f[9];
        features9(v, f);
#pragma unroll
        for (int g = 0; g < 9; ++g) SA[i][c * 9 + g] = __float2half(f[g]);
    }
    __syncthreads();

#pragma unroll
    for (int u = t; u < 1152; u += 256) {
        int row = u / 36;
        int col = (u - row * 36) * 8;
        const uint32_t* pa = (const uint32_t*)&SA[row][col];
        uint4 va; va.x = pa[0]; va.y = pa[1]; va.z = pa[2]; va.w = pa[3];
        *(uint4*)&g_A[(size_t)(m0 + row) * KDIM + col] = va;
    }
}

// ---------------- kernel 2: fold weights -> fp16 ----------------
__global__ void fold_kernel(const float* __restrict__ bw,
                            const float* __restrict__ sw,
                            const float* __restrict__ ss) {
    int i = blockIdx.x * blockDim.x + threadIdx.x;    // [tap][n][k]
    if (i >= 9 * 64 * KDIM) return;
    int k = i % KDIM;
    int n = (i / KDIM) & 63;
    int p = i / (KDIM * 64);
    int c = k / 9, g = k % 9;
    int ocp = (n * CIN + c) * 9 + p;
    float val = (g == 0) ? bw[ocp] : sw[ocp * 8 + (g - 1)] * ss[ocp];
    g_B[i] = __float2half(val);
}

// ---------------- kernel 3: mma.sync fp16 GEMM, M=128, shifted-A, occ 2 ---
// Single accumulator per output: tap (kh,kw) loads A at row offset kh*64+kw.
// smem per buffer: A[258 rows -> 260][48B] = 12480; B[9][64][48] = 27648
// BUFSZ = 40128, double buffered = 80256 B; 2 CTAs/SM = 160.5 KB.
#define APITCH 48
#define AROWS  260                       // need 258 (126+128+2+pad)
#define BOFF   (AROWS * APITCH)          // 12480
#define BTILE  (64 * APITCH)             // 3072
#define BUFSZ  (BOFF + 9 * BTILE)        // 40128
#define SMEM_TOT (2 * BUFSZ)             // 80256

__global__ void __launch_bounds__(256, 2) gemm_kernel(float* __restrict__ out) {
    extern __shared__ __align__(16) char smem[];
    uint32_t sb = smem_u32(smem);
    const int tid  = threadIdx.x;
    const int lane = tid & 31;
    const int wid  = tid >> 5;
    const int mw = wid & 3;              // m-warp: rows mw*32..+32
    const int nw = wid >> 2;             // n-warp: cols nw*32..+32
    const int m0 = blockIdx.x * MOUT;

    const char* Ap = (const char*)g_A;
    const char* Bp = (const char*)g_B;

    // per-kc: A 258 rows x 2 halves = 516, B 9*64*2 = 1152 -> 1668 ops
    auto prefetch = [&](int kc, uint32_t bb) {
#pragma unroll
        for (int i = 0; i < 7; ++i) {
            int u = tid + i * 256;
            if (u >= 1668) break;
            const char* src;
            uint32_t dst;
            if (u < 516) {
                int row = u >> 1, half = u & 1;
                src = Ap + (size_t)(m0 + row) * (KDIM * 2) + kc * 32 + half * 16;
                dst = bb + row * APITCH + half * 16;
            } else {
                int v = u - 516;
                int tile = v >> 7, row = (v >> 1) & 63, half = v & 1;
                src = Bp + (size_t)(tile * 64 + row) * (KDIM * 2) + kc * 32 + half * 16;
                dst = bb + BOFF + tile * BTILE + row * APITCH + half * 16;
            }
            cp16(dst, src);
        }
    };

    float acc[2][4][4];                  // [t2][nf][4] -- single output acc
#pragma unroll
    for (int b = 0; b < 2; ++b)
#pragma unroll
        for (int c = 0; c < 4; ++c)
#pragma unroll
            for (int d = 0; d < 4; ++d) acc[b][c][d] = 0.0f;

    const uint32_t a_lane = (uint32_t)((lane & 15) * APITCH + (lane >> 4) * 16);
    const uint32_t b_lane = (uint32_t)((lane & 7) * APITCH + ((lane >> 3) & 1) * 16);

    prefetch(0, sb);
    CP_COMMIT();

    for (int kc = 0; kc < 18; ++kc) {
        if (kc < 17) prefetch(kc + 1, sb + ((kc + 1) & 1) * BUFSZ);
        CP_COMMIT();
        CP_WAIT1();
        __syncthreads();

        const uint32_t bb = sb + (kc & 1) * BUFSZ;
#pragma unroll
        for (int kh = 0; kh < 3; ++kh)
#pragma unroll
            for (int kw = 0; kw < 3; ++kw) {
                // A fragment shifted by the tap offset (row kh*64 + kw)
                uint32_t ah[2][4];
#pragma unroll
                for (int t2 = 0; t2 < 2; ++t2) {
                    uint32_t ra = bb + (kh * 64 + kw + mw * 32 + t2 * 16) * APITCH + a_lane;
                    LDSM4(ah[t2], ra);
                }
                const int tile = kh * 3 + kw;
#pragma unroll
                for (int nf = 0; nf < 4; ++nf) {
                    uint32_t rb = bb + BOFF + tile * BTILE
                                + (nw * 32 + nf * 8) * APITCH + b_lane;
                    uint32_t bfr[2];
                    LDSM2(bfr, rb);
#pragma unroll
                    for (int t2 = 0; t2 < 2; ++t2)
                        MMA(acc[t2][nf], ah[t2], bfr);
                }
            }
        __syncthreads();
    }

    CP_WAITALL();

    // ---- epilogue: registers -> gmem directly (no staging) ----
    const int grp = lane >> 2;
    const int cq  = (lane & 3) * 2;
#pragma unroll
    for (int t2 = 0; t2 < 2; ++t2) {
#pragma unroll
        for (int j2 = 0; j2 < 2; ++j2) {          // row / row+8
            int r = mw * 32 + t2 * 16 + grp + j2 * 8;
            int m = m0 + r;
            if (r < MOUT && m < MTOT) {
                int h = (m >> 6) & 63, w = m & 63, b = m >> 12;
                if (h < HO && w < WO) {
                    size_t obase = ((size_t)b * COUT) * (HO * WO) + h * WO + w;
#pragma unroll
                    for (int nf = 0; nf < 4; ++nf) {
                        int o = nw * 32 + nf * 8 + cq;
                        out[obase + (size_t)o * (HO * WO)]       = acc[t2][nf][j2 * 2];
                        out[obase + (size_t)(o + 1) * (HO * WO)] = acc[t2][nf][j2 * 2 + 1];
                    }
                }
            }
        }
    }
}

// ---------------- launch ----------------
extern "C" void kernel_launch(void* const* d_in, const int* in_sizes, int n_in,
                              void* d_out, int out_size) {
    const float* x  = (const float*)d_in[0];
    const float* bw = (const float*)d_in[1];
    const float* sw = (const float*)d_in[2];
    const float* ss = (const float*)d_in[3];
    float* out = (float*)d_out;

    static int smem_set = 0;
    if (!smem_set) {
        cudaFuncSetAttribute(gemm_kernel, cudaFuncAttributeMaxDynamicSharedMemorySize, SMEM_TOT);
        smem_set = 1;
    }

    feat_kernel<<<MTOT / 32, 256>>>(x);
    fold_kernel<<<(9 * 64 * KDIM + 255) / 256, 256>>>(bw, sw, ss);
    gemm_kernel<<<NCTA, 256, SMEM_TOT>>>(out);
}

// round 10
// speedup vs baseline: 1.2748x; 1.0500x over previous
#include <cuda_runtime.h>
#include <cuda_fp16.h>
#include <cstdint>

// ---------------- problem constants ----------------
#define B_    16
#define CIN   32
#define COUT  64
#define HO    62
#define WO    62
#define HW    4096
#define KDIM  288          // (c,g) = 32*9
#define MTOT  65536        // b*h*w pixels
#define MPAD  65800
#define MOUT  126          // output rows per CTA
#define NCTA  521

// ---------------- device scratch ----------------
__device__ __align__(16) __half g_A[(size_t)MPAD * KDIM];   // fp16 features
__device__ __align__(16) __half g_B[9 * 64 * KDIM];         // [tap][n][k] fp16

// ---------------- helpers ----------------
__device__ __forceinline__ uint32_t smem_u32(const void* p) {
    uint32_t a;
    asm("{ .reg .u64 t; cvta.to.shared.u64 t, %1; cvt.u32.u64 %0, t; }" : "=r"(a) : "l"(p));
    return a;
}
__device__ __forceinline__ void cp16(uint32_t dst, const void* src) {
    asm volatile("cp.async.cg.shared.global [%0], [%1], 16;" :: "r"(dst), "l"(src));
}
#define CP_COMMIT() asm volatile("cp.async.commit_group;" ::: "memory")
#define CP_WAIT1()  asm volatile("cp.async.wait_group 1;" ::: "memory")
#define CP_WAITALL() asm volatile("cp.async.wait_all;" ::: "memory")

#define LDSM4(r, a)                                                          \
    asm volatile("ldmatrix.sync.aligned.m8n8.x4.shared.b16 {%0,%1,%2,%3}, [%4];" \
        : "=r"((r)[0]), "=r"((r)[1]), "=r"((r)[2]), "=r"((r)[3]) : "r"(a))
#define LDSM2(r, a)                                                          \
    asm volatile("ldmatrix.sync.aligned.m8n8.x2.shared.b16 {%0,%1}, [%2];"   \
        : "=r"((r)[0]), "=r"((r)[1]) : "r"(a))
#define MMA(d, a, b)                                                         \
    asm volatile("mma.sync.aligned.m16n8k16.row.col.f32.f16.f16.f32 "        \
        "{%0,%1,%2,%3}, {%4,%5,%6,%7}, {%8,%9}, {%0,%1,%2,%3};"              \
        : "+f"((d)[0]), "+f"((d)[1]), "+f"((d)[2]), "+f"((d)[3])             \
        : "r"((a)[0]), "r"((a)[1]), "r"((a)[2]), "r"((a)[3]),                \
          "r"((b)[0]), "r"((b)[1]))

// ---------------- kernel 1: features -> fp16 A (direct B-spline eval) -----
#define SROW 290
__global__ void __launch_bounds__(256) feat_kernel(const float* __restrict__ x) {
    __shared__ __half SA[32][SROW];
    const int m0  = blockIdx.x * 32;
    const int b   = m0 >> 12;
    const int hw0 = m0 & 4095;
    const int t   = threadIdx.x;
    const int i   = t & 31;
    const int c0  = t >> 5;

#pragma unroll
    for (int cc = 0; cc < 4; ++cc) {
        int c = c0 + cc * 8;
        float v = x[((size_t)(b * CIN + c) << 12) + hw0 + i];
        __half* row = &SA[i][c * 9];
        // SiLU
        row[0] = __float2half(__fdividef(v, 1.0f + __expf(-v)));
        // zero the 8 basis slots
#pragma unroll
        for (int g = 1; g < 9; ++g) row[g] = __ushort_as_half((unsigned short)0);
        // cubic B-spline: at most 4 nonzero bases
        float s = (v + 2.2f) * 2.5f;
        float fs = floorf(s);
        int idx = (int)fs;
        if (idx >= 0 && idx <= 10) {
            float u  = s - fs;
            float um = 1.0f - u;
            float u2 = u * u, u3 = u2 * u;
            const float k6 = 1.0f / 6.0f;
            float w0 = um * um * um * k6;
            float w1 = (3.0f * u3 - 6.0f * u2 + 4.0f) * k6;
            float w2 = (-3.0f * u3 + 3.0f * u2 + 3.0f * u + 1.0f) * k6;
            float w3 = u3 * k6;
            int j = idx - 3;                 // first nonzero basis index
            if (j     >= 0 && j     <= 7) row[1 + j]     = __float2half(w0);
            if (j + 1 >= 0 && j + 1 <= 7) row[2 + j]     = __float2half(w1);
            if (j + 2 >= 0 && j + 2 <= 7) row[3 + j]     = __float2half(w2);
            if (j + 3 >= 0 && j + 3 <= 7) row[4 + j]     = __float2half(w3);
        }
    }
    __syncthreads();

#pragma unroll
    for (int u = t; u < 1152; u += 256) {
        int row = u / 36;
        int col = (u - row * 36) * 8;
        const uint32_t* pa = (const uint32_t*)&SA[row][col];
        uint4 va; va.x = pa[0]; va.y = pa[1]; va.z = pa[2]; va.w = pa[3];
        *(uint4*)&g_A[(size_t)(m0 + row) * KDIM + col] = va;
    }
}

// ---------------- kernel 2: fold weights -> fp16 ----------------
__global__ void fold_kernel(const float* __restrict__ bw,
                            const float* __restrict__ sw,
                            const float* __restrict__ ss) {
    int i = blockIdx.x * blockDim.x + threadIdx.x;    // [tap][n][k]
    if (i >= 9 * 64 * KDIM) return;
    int k = i % KDIM;
    int n = (i / KDIM) & 63;
    int p = i / (KDIM * 64);
    int c = k / 9, g = k % 9;
    int ocp = (n * CIN + c) * 9 + p;
    float val = (g == 0) ? bw[ocp] : sw[ocp * 8 + (g - 1)] * ss[ocp];
    g_B[i] = __float2half(val);
}

// ---------------- kernel 3: mma.sync fp16 GEMM, M=128, shifted-A, occ 2 ---
#define APITCH 48
#define AROWS  260
#define BOFF   (AROWS * APITCH)          // 12480
#define BTILE  (64 * APITCH)             // 3072
#define BUFSZ  (BOFF + 9 * BTILE)        // 40128
#define SMEM_TOT (2 * BUFSZ)             // 80256

__global__ void __launch_bounds__(256, 2) gemm_kernel(float* __restrict__ out) {
    extern __shared__ __align__(16) char smem[];
    uint32_t sb = smem_u32(smem);
    const int tid  = threadIdx.x;
    const int lane = tid & 31;
    const int wid  = tid >> 5;
    const int mw = wid & 3;
    const int nw = wid >> 2;
    const int m0 = blockIdx.x * MOUT;

    const char* Ap = (const char*)g_A;
    const char* Bp = (const char*)g_B;

    auto prefetch = [&](int kc, uint32_t bb) {
#pragma unroll
        for (int i = 0; i < 7; ++i) {
            int u = tid + i * 256;
            if (u >= 1668) break;
            const char* src;
            uint32_t dst;
            if (u < 516) {
                int row = u >> 1, half = u & 1;
                src = Ap + (size_t)(m0 + row) * (KDIM * 2) + kc * 32 + half * 16;
                dst = bb + row * APITCH + half * 16;
            } else {
                int v = u - 516;
                int tile = v >> 7, row = (v >> 1) & 63, half = v & 1;
                src = Bp + (size_t)(tile * 64 + row) * (KDIM * 2) + kc * 32 + half * 16;
                dst = bb + BOFF + tile * BTILE + row * APITCH + half * 16;
            }
            cp16(dst, src);
        }
    };

    float acc[2][4][4];
#pragma unroll
    for (int b = 0; b < 2; ++b)
#pragma unroll
        for (int c = 0; c < 4; ++c)
#pragma unroll
            for (int d = 0; d < 4; ++d) acc[b][c][d] = 0.0f;

    const uint32_t a_lane = (uint32_t)((lane & 15) * APITCH + (lane >> 4) * 16);
    const uint32_t b_lane = (uint32_t)((lane & 7) * APITCH + ((lane >> 3) & 1) * 16);

    prefetch(0, sb);
    CP_COMMIT();

    for (int kc = 0; kc < 18; ++kc) {
        if (kc < 17) prefetch(kc + 1, sb + ((kc + 1) & 1) * BUFSZ);
        CP_COMMIT();
        CP_WAIT1();
        __syncthreads();

        const uint32_t bb = sb + (kc & 1) * BUFSZ;
#pragma unroll
        for (int kh = 0; kh < 3; ++kh)
#pragma unroll
            for (int kw = 0; kw < 3; ++kw) {
                uint32_t ah[2][4];
#pragma unroll
                for (int t2 = 0; t2 < 2; ++t2) {
                    uint32_t ra = bb + (kh * 64 + kw + mw * 32 + t2 * 16) * APITCH + a_lane;
                    LDSM4(ah[t2], ra);
                }
                const int tile = kh * 3 + kw;
#pragma unroll
                for (int nf = 0; nf < 4; ++nf) {
                    uint32_t rb = bb + BOFF + tile * BTILE
                                + (nw * 32 + nf * 8) * APITCH + b_lane;
                    uint32_t bfr[2];
                    LDSM2(bfr, rb);
#pragma unroll
                    for (int t2 = 0; t2 < 2; ++t2)
                        MMA(acc[t2][nf], ah[t2], bfr);
                }
            }
        __syncthreads();
    }

    CP_WAITALL();

    // ---- epilogue: registers -> gmem directly ----
    const int grp = lane >> 2;
    const int cq  = (lane & 3) * 2;
#pragma unroll
    for (int t2 = 0; t2 < 2; ++t2) {
#pragma unroll
        for (int j2 = 0; j2 < 2; ++j2) {
            int r = mw * 32 + t2 * 16 + grp + j2 * 8;
            int m = m0 + r;
            if (r < MOUT && m < MTOT) {
                int h = (m >> 6) & 63, w = m & 63, b = m >> 12;
                if (h < HO && w < WO) {
                    size_t obase = ((size_t)b * COUT) * (HO * WO) + h * WO + w;
#pragma unroll
                    for (int nf = 0; nf < 4; ++nf) {
                        int o = nw * 32 + nf * 8 + cq;
                        out[obase + (size_t)o * (HO * WO)]       = acc[t2][nf][j2 * 2];
                        out[obase + (size_t)(o + 1) * (HO * WO)] = acc[t2][nf][j2 * 2 + 1];
                    }
                }
            }
        }
    }
}

// ---------------- launch ----------------
extern "C" void kernel_launch(void* const* d_in, const int* in_sizes, int n_in,
                              void* d_out, int out_size) {
    const float* x  = (const float*)d_in[0];
    const float* bw = (const float*)d_in[1];
    const float* sw = (const float*)d_in[2];
    const float* ss = (const float*)d_in[3];
    float* out = (float*)d_out;

    static int smem_set = 0;
    if (!smem_set) {
        cudaFuncSetAttribute(gemm_kernel, cudaFuncAttributeMaxDynamicSharedMemorySize, SMEM_TOT);
        smem_set = 1;
    }

    feat_kernel<<<MTOT / 32, 256>>>(x);
    fold_kernel<<<(9 * 64 * KDIM + 255) / 256, 256>>>(bw, sw, ss);
    gemm_kernel<<<NCTA, 256, SMEM_TOT>>>(out);
}